// round 2
// baseline (speedup 1.0000x reference)
#include <cuda_runtime.h>
#include <cuda_bf16.h>

// Problem constants (fixed by the reference):
//   E = 200000 edges, D = 128, MID = 512, OUT = 128, NTYPES = 8
//   inputs: from_embeddings[E,128] f32, to_embeddings[E,128] f32,
//           edge_types[E] int64-or-int32, W1[256,512] f32, b1[512] f32,
//           W2[512,1024] f32, b2[1024] f32
//   output: [E,128] f32
//
// Strategy:
//   1. bucket edges by type (counting sort, groups padded to multiples of 64)
//   2. fused per-block kernel: 64 edges, GEMM1 (256->512) chunked by 128 cols,
//      ReLU, then GEMM2 against the single W2 128-col slice for the block's
//      type (8x less GEMM2 work than computing all 1024 cols).
//   3. packed fp32 math via PTX fma.rn.f32x2 (SASS FFMA2, 2x fp32 rate).

#define MAXPERM (1 << 18)   // >= E + 8*64

__device__ int g_perm[MAXPERM];
__device__ int g_counts[8];
__device__ int g_off[9];      // padded group offsets, g_off[8] = padded total
__device__ int g_cursor[8];
__device__ int g_is64;

// ---------------------------------------------------------------- helpers
__device__ __forceinline__ unsigned long long pk2(float a, float b) {
    unsigned long long r;
    asm("mov.b64 %0, {%1, %2};" : "=l"(r) : "f"(a), "f"(b));
    return r;
}
__device__ __forceinline__ void upk2(unsigned long long v, float& a, float& b) {
    asm("mov.b64 {%0, %1}, %2;" : "=f"(a), "=f"(b) : "l"(v));
}
__device__ __forceinline__ unsigned long long ffma2(unsigned long long a,
                                                    unsigned long long b,
                                                    unsigned long long c) {
    unsigned long long d;
    asm("fma.rn.f32x2 %0, %1, %2, %3;" : "=l"(d) : "l"(a), "l"(b), "l"(c));
    return d;
}
__device__ __forceinline__ int get_type(const void* p, int e, int is64) {
    return is64 ? (int)(((const long long*)p)[e]) : ((const int*)p)[e];
}

// ------------------------------------------------------- preprocessing
// Detect whether edge_types is int64 (little-endian high words all zero) or
// int32. Reads only the first 128 int32 slots -> in-bounds for either dtype.
__global__ void k_detect(const int* __restrict__ p, int E) {
    if (threadIdx.x == 0 && blockIdx.x == 0) {
        int n = (E >= 128) ? 64 : (E >> 1);
        int is64 = 1;
        for (int k = 0; k < n; k++)
            if (p[2 * k + 1] != 0) { is64 = 0; break; }
        g_is64 = is64;
        for (int t = 0; t < 8; t++) g_counts[t] = 0;
    }
}

__global__ void k_fill(int n) {
    int i = blockIdx.x * 256 + threadIdx.x;
    if (i < n) g_perm[i] = -1;
}

__global__ void k_count(const void* __restrict__ et, int E) {
    __shared__ int h[8];
    int tid = threadIdx.x;
    if (tid < 8) h[tid] = 0;
    __syncthreads();
    int e = blockIdx.x * 256 + tid;
    int is64 = g_is64;
    if (e < E) atomicAdd(&h[get_type(et, e, is64)], 1);
    __syncthreads();
    if (tid < 8 && h[tid] > 0) atomicAdd(&g_counts[tid], h[tid]);
}

__global__ void k_scan() {
    if (threadIdx.x == 0 && blockIdx.x == 0) {
        int pot = 0;
        for (int t = 0; t < 8; t++) {
            g_off[t] = pot;
            g_cursor[t] = pot;
            pot += ((g_counts[t] + 63) >> 6) << 6;   // pad group to 64
        }
        g_off[8] = pot;
    }
}

__global__ void k_scatter(const void* __restrict__ et, int E) {
    __shared__ int cnt[8];
    int tid = threadIdx.x;
    if (tid < 8) cnt[tid] = 0;
    __syncthreads();
    int e = blockIdx.x * 256 + tid;
    int t = -1;
    int is64 = g_is64;
    if (e < E) { t = get_type(et, e, is64); atomicAdd(&cnt[t], 1); }
    __syncthreads();
    if (tid < 8) {
        int c = cnt[tid];
        cnt[tid] = (c > 0) ? atomicAdd(&g_cursor[tid], c) : 0;
    }
    __syncthreads();
    if (t >= 0) {
        int pos = atomicAdd(&cnt[t], 1);
        g_perm[pos] = e;
    }
}

// ------------------------------------------------------------ main kernel
// Block: 256 threads as 16x16 grid, 64 edges, one edge-type per block.
// Dynamic smem:
//   sAT  [256][64]  f32   A transposed (k-major)               65536 B
//   sHT  [128][64]  f32   H chunk transposed, XOR-swizzled     32768 B
//   sW   [32][132]  f32   W tile (stride 132 = pad)            16896 B
//   sIdx [64]       i32                                          256 B
#define SMEM_FLOATS (16384 + 8192 + 4224)
#define SMEM_BYTES  (SMEM_FLOATS * 4 + 256)

__global__ __launch_bounds__(256, 1)
void k_main(const float* __restrict__ fromE, const float* __restrict__ toE,
            const float* __restrict__ W1, const float* __restrict__ b1,
            const float* __restrict__ W2, const float* __restrict__ b2,
            float* __restrict__ out) {
    extern __shared__ float smem[];
    float* sAT = smem;                  // [k 0..255][i 0..63]
    float* sHT = smem + 16384;          // [c 0..127][swizzled r 0..63]
    float* sW  = smem + 24576;          // [kk 0..31][c 0..127] stride 132
    int*  sIdx = (int*)(smem + SMEM_FLOATS);

    const int tid = threadIdx.x;
    const int tx = tid & 15;            // output-column group
    const int ty = tid >> 4;            // edge-row group

    const int p0 = blockIdx.x * 64;
    if (p0 >= g_off[8]) return;

    int type = 0;
    #pragma unroll
    for (int t = 1; t < 8; t++)
        if (p0 >= g_off[t]) type = t;
    const int tbase = type * 128;

    if (tid < 64) sIdx[tid] = g_perm[p0 + tid];
    __syncthreads();

    // ---- gather A = concat(from,to) into sAT[k][i]
    #pragma unroll
    for (int j = 0; j < 16; j++) {
        int s = tid + j * 256;          // 4096 float4 slots
        int i = s & 63, q = s >> 6;     // q = k/4
        int e = sIdx[i];
        float4 v = make_float4(0.f, 0.f, 0.f, 0.f);
        if (e >= 0) {
            const float* src = (q < 32) ? (fromE + (size_t)e * 128 + q * 4)
                                        : (toE   + (size_t)e * 128 + (q - 32) * 4);
            v = *(const float4*)src;
        }
        float* dst = sAT + (q * 4) * 64 + i;
        dst[0] = v.x; dst[64] = v.y; dst[128] = v.z; dst[192] = v.w;
    }

    // ---- init output accumulators with b2 slice (packed f32x2)
    unsigned long long oacc[4][4];
    {
        const float* bp = b2 + tbase + tx * 8;
        #pragma unroll
        for (int jj = 0; jj < 4; jj++) {
            unsigned long long v = pk2(bp[2 * jj], bp[2 * jj + 1]);
            #pragma unroll
            for (int i = 0; i < 4; i++) oacc[i][jj] = v;
        }
    }
    __syncthreads();

    #pragma unroll 1
    for (int nc = 0; nc < 4; nc++) {    // 128-col chunk of H
        // ---- GEMM1: hacc = A @ W1[:, nc*128 : nc*128+128] + b1
        unsigned long long hacc[4][4];
        {
            const float* bp = b1 + nc * 128 + tx * 8;
            #pragma unroll
            for (int jj = 0; jj < 4; jj++) {
                unsigned long long v = pk2(bp[2 * jj], bp[2 * jj + 1]);
                #pragma unroll
                for (int i = 0; i < 4; i++) hacc[i][jj] = v;
            }
        }
        #pragma unroll 1
        for (int kt = 0; kt < 8; kt++) {
            #pragma unroll
            for (int r = 0; r < 4; r++) {
                int slot = tid + r * 256;
                int kk = slot >> 5, cq = slot & 31;
                float4 wv = *(const float4*)(W1 + (size_t)(kt * 32 + kk) * 512
                                             + nc * 128 + cq * 4);
                *(float4*)(sW + kk * 132 + cq * 4) = wv;
            }
            __syncthreads();
            #pragma unroll 8
            for (int kk = 0; kk < 32; kk++) {
                float4 av = *(const float4*)(sAT + (kt * 32 + kk) * 64 + ty * 4);
                ulonglong2 bv0 = *(const ulonglong2*)(sW + kk * 132 + tx * 8);
                ulonglong2 bv1 = *(const ulonglong2*)(sW + kk * 132 + tx * 8 + 4);
                float ar[4] = {av.x, av.y, av.z, av.w};
                #pragma unroll
                for (int i = 0; i < 4; i++) {
                    unsigned long long a2 = pk2(ar[i], ar[i]);
                    hacc[i][0] = ffma2(a2, bv0.x, hacc[i][0]);
                    hacc[i][1] = ffma2(a2, bv0.y, hacc[i][1]);
                    hacc[i][2] = ffma2(a2, bv1.x, hacc[i][2]);
                    hacc[i][3] = ffma2(a2, bv1.y, hacc[i][3]);
                }
            }
            __syncthreads();
        }

        // ---- ReLU + swizzled transpose into sHT[c][r ^ (tx*4)]
        #pragma unroll
        for (int i = 0; i < 4; i++) {
            int r = ty * 4 + i;
            int rs = r ^ (tx * 4);      // swizzle s(c) = (c>>3)<<2, c>>3 == tx
            #pragma unroll
            for (int jj = 0; jj < 4; jj++) {
                float x, y;
                upk2(hacc[i][jj], x, y);
                x = fmaxf(x, 0.f); y = fmaxf(y, 0.f);
                int c = tx * 8 + jj * 2;
                sHT[c * 64 + rs] = x;
                sHT[(c + 1) * 64 + rs] = y;
            }
        }
        __syncthreads();

        // ---- GEMM2 partial: oacc += Hchunk @ W2[chunk_k, tbase:tbase+128]
        #pragma unroll 1
        for (int kt2 = 0; kt2 < 4; kt2++) {
            #pragma unroll
            for (int r = 0; r < 4; r++) {
                int slot = tid + r * 256;
                int kk = slot >> 5, cq = slot & 31;
                float4 wv = *(const float4*)(W2 + (size_t)(nc * 128 + kt2 * 32 + kk) * 1024
                                             + tbase + cq * 4);
                *(float4*)(sW + kk * 132 + cq * 4) = wv;
            }
            __syncthreads();
            #pragma unroll 8
            for (int kk = 0; kk < 32; kk++) {
                int kkg = kt2 * 32 + kk;
                int sbase = kkg * 64 + ((ty * 4) ^ (((kkg >> 3) & 15) << 2));
                float4 hv = *(const float4*)(sHT + sbase);
                ulonglong2 bv0 = *(const ulonglong2*)(sW + kk * 132 + tx * 8);
                ulonglong2 bv1 = *(const ulonglong2*)(sW + kk * 132 + tx * 8 + 4);
                float hr[4] = {hv.x, hv.y, hv.z, hv.w};
                #pragma unroll
                for (int i = 0; i < 4; i++) {
                    unsigned long long a2 = pk2(hr[i], hr[i]);
                    oacc[i][0] = ffma2(a2, bv0.x, oacc[i][0]);
                    oacc[i][1] = ffma2(a2, bv0.y, oacc[i][1]);
                    oacc[i][2] = ffma2(a2, bv1.x, oacc[i][2]);
                    oacc[i][3] = ffma2(a2, bv1.y, oacc[i][3]);
                }
            }
            __syncthreads();
        }
    }

    // ---- scatter results back to original edge rows
    #pragma unroll
    for (int i = 0; i < 4; i++) {
        int e = sIdx[ty * 4 + i];
        if (e >= 0) {
            float4 o0, o1;
            upk2(oacc[i][0], o0.x, o0.y);
            upk2(oacc[i][1], o0.z, o0.w);
            upk2(oacc[i][2], o1.x, o1.y);
            upk2(oacc[i][3], o1.z, o1.w);
            *(float4*)(out + (size_t)e * 128 + tx * 8)     = o0;
            *(float4*)(out + (size_t)e * 128 + tx * 8 + 4) = o1;
        }
    }
}

// ---------------------------------------------------------------- launch
extern "C" void kernel_launch(void* const* d_in, const int* in_sizes, int n_in,
                              void* d_out, int out_size) {
    const float* fromE = (const float*)d_in[0];
    const float* toE   = (const float*)d_in[1];
    const void*  et    = d_in[2];
    const float* W1    = (const float*)d_in[3];
    const float* b1    = (const float*)d_in[4];
    const float* W2    = (const float*)d_in[5];
    const float* b2    = (const float*)d_in[6];
    float* out = (float*)d_out;

    const int E = in_sizes[0] / 128;
    const int padcap = E + 8 * 64;

    cudaFuncSetAttribute(k_main, cudaFuncAttributeMaxDynamicSharedMemorySize,
                         SMEM_BYTES);

    k_detect<<<1, 32>>>((const int*)et, E);
    k_fill<<<(padcap + 255) / 256, 256>>>(padcap);
    k_count<<<(E + 255) / 256, 256>>>(et, E);
    k_scan<<<1, 32>>>();
    k_scatter<<<(E + 255) / 256, 256>>>(et, E);

    const int nMain = (E + 63) / 64 + 8;
    k_main<<<nMain, 256, SMEM_BYTES>>>(fromE, toE, W1, b1, W2, b2, out);
}

// round 5
// speedup vs baseline: 4.1687x; 4.1687x over previous
#include <cuda_runtime.h>
#include <cuda_bf16.h>
#include <cstdint>

// ============================================================================
// PointMessagePassing on plain sm_100 ISA (ptxas target has no 'a' suffix, so
// tcgen05 is unavailable). Tensor path: mma.sync.m16n8k16 bf16 + ldmatrix +
// cp.async. fp32 accuracy via 3-term bf16 split (AhBh + AlBh + AhBl).
//
// Per block: 128 edges of ONE type. 8 warps x 16 rows each, end-to-end:
//   GEMM1 chunk (N=128 of 512): Hacc in regs -> bias+ReLU+split in regs ->
//   GEMM2 consumes H straight from registers (C-frag == A-frag layout trick),
//   accumulating Out[16,128] per warp across the 4 chunks. H never in smem.
// ============================================================================

#define MAXPERM (1 << 18)

__device__ int g_perm[MAXPERM];
__device__ int g_counts[8];
__device__ int g_off[9];
__device__ int g_cursor[8];
__device__ int g_is64;

// pre-split / transposed weights (bf16 hi/lo), n-major k-contiguous:
__device__ __align__(16) __nv_bfloat16 g_w1h[512 * 256];
__device__ __align__(16) __nv_bfloat16 g_w1l[512 * 256];
__device__ __align__(16) __nv_bfloat16 g_w2h[1024 * 512];
__device__ __align__(16) __nv_bfloat16 g_w2l[1024 * 512];

// ---------------------------------------------------------------- helpers
__device__ __forceinline__ uint32_t smem_u32(const void* p) {
    uint32_t a;
    asm("{ .reg .u64 t; cvta.to.shared.u64 t, %1; cvt.u32.u64 %0, t; }"
        : "=r"(a) : "l"(p));
    return a;
}
__device__ __forceinline__ uint32_t swz(uint32_t off) {
    return off ^ ((off >> 3) & 0x70);
}
__device__ __forceinline__ void split2(float x, float y, uint32_t& h, uint32_t& l) {
    __nv_bfloat16 hx = __float2bfloat16(x), hy = __float2bfloat16(y);
    __nv_bfloat16 lx = __float2bfloat16(x - __bfloat162float(hx));
    __nv_bfloat16 ly = __float2bfloat16(y - __bfloat162float(hy));
    h = (uint32_t)__bfloat16_as_ushort(hx) | ((uint32_t)__bfloat16_as_ushort(hy) << 16);
    l = (uint32_t)__bfloat16_as_ushort(lx) | ((uint32_t)__bfloat16_as_ushort(ly) << 16);
}
__device__ __forceinline__ int get_type(const void* p, int e, int is64) {
    return is64 ? (int)(((const long long*)p)[e]) : ((const int*)p)[e];
}
__device__ __forceinline__ void ldsm4(uint32_t* r, uint32_t addr) {
    asm volatile("ldmatrix.sync.aligned.m8n8.x4.shared.b16 {%0,%1,%2,%3}, [%4];"
        : "=r"(r[0]), "=r"(r[1]), "=r"(r[2]), "=r"(r[3]) : "r"(addr));
}
__device__ __forceinline__ void mma16816(float* d, const uint32_t* a,
                                         uint32_t b0, uint32_t b1) {
    asm volatile(
        "mma.sync.aligned.m16n8k16.row.col.f32.bf16.bf16.f32 "
        "{%0,%1,%2,%3}, {%4,%5,%6,%7}, {%8,%9}, {%0,%1,%2,%3};"
        : "+f"(d[0]), "+f"(d[1]), "+f"(d[2]), "+f"(d[3])
        : "r"(a[0]), "r"(a[1]), "r"(a[2]), "r"(a[3]), "r"(b0), "r"(b1));
}
__device__ __forceinline__ void cpa16(uint32_t dst, const void* src) {
    asm volatile("cp.async.cg.shared.global [%0], [%1], 16;"
                 :: "r"(dst), "l"(src));
}
__device__ __forceinline__ void cp_commit() {
    asm volatile("cp.async.commit_group;");
}
__device__ __forceinline__ void cp_wait1() {
    asm volatile("cp.async.wait_group 1;");
}
__device__ __forceinline__ void cp_wait0() {
    asm volatile("cp.async.wait_group 0;");
}

// ------------------------------------------------------- preprocessing
__global__ void k_detect(const int* __restrict__ p, int E) {
    if (threadIdx.x == 0 && blockIdx.x == 0) {
        int n = (E >= 128) ? 64 : (E >> 1);
        int is64 = 1;
        for (int k = 0; k < n; k++)
            if (p[2 * k + 1] != 0) { is64 = 0; break; }
        g_is64 = is64;
        for (int t = 0; t < 8; t++) g_counts[t] = 0;
    }
}
__global__ void k_fill(int n) {
    int i = blockIdx.x * 256 + threadIdx.x;
    if (i < n) g_perm[i] = -1;
}
__global__ void k_count(const void* __restrict__ et, int E) {
    __shared__ int h[8];
    int tid = threadIdx.x;
    if (tid < 8) h[tid] = 0;
    __syncthreads();
    int e = blockIdx.x * 256 + tid;
    int is64 = g_is64;
    if (e < E) atomicAdd(&h[get_type(et, e, is64)], 1);
    __syncthreads();
    if (tid < 8 && h[tid] > 0) atomicAdd(&g_counts[tid], h[tid]);
}
__global__ void k_scan() {
    if (threadIdx.x == 0 && blockIdx.x == 0) {
        int pot = 0;
        for (int t = 0; t < 8; t++) {
            g_off[t] = pot;
            g_cursor[t] = pot;
            pot += ((g_counts[t] + 127) >> 7) << 7;   // pad group to 128
        }
        g_off[8] = pot;
    }
}
__global__ void k_scatter(const void* __restrict__ et, int E) {
    __shared__ int cnt[8];
    int tid = threadIdx.x;
    if (tid < 8) cnt[tid] = 0;
    __syncthreads();
    int e = blockIdx.x * 256 + tid;
    int t = -1;
    int is64 = g_is64;
    if (e < E) { t = get_type(et, e, is64); atomicAdd(&cnt[t], 1); }
    __syncthreads();
    if (tid < 8) {
        int c = cnt[tid];
        cnt[tid] = (c > 0) ? atomicAdd(&g_cursor[tid], c) : 0;
    }
    __syncthreads();
    if (t >= 0) {
        int pos = atomicAdd(&cnt[t], 1);
        g_perm[pos] = e;
    }
}
// split + transpose weights into bf16 hi/lo scratch (n-major, k-contiguous)
__global__ void k_convw(const float* __restrict__ W1, const float* __restrict__ W2) {
    int i = blockIdx.x * 256 + threadIdx.x;
    if (i < 256 * 512) {
        int k = i >> 9, n = i & 511;
        float x = W1[i];
        __nv_bfloat16 h = __float2bfloat16(x);
        __nv_bfloat16 l = __float2bfloat16(x - __bfloat162float(h));
        g_w1h[n * 256 + k] = h;
        g_w1l[n * 256 + k] = l;
    }
    if (i < 512 * 1024) {
        int k = i >> 10, n = i & 1023;
        float x = W2[i];
        __nv_bfloat16 h = __float2bfloat16(x);
        __nv_bfloat16 l = __float2bfloat16(x - __bfloat162float(h));
        g_w2h[n * 512 + k] = h;
        g_w2l[n * 512 + k] = l;
    }
}

// ------------------------------------------------------------ main kernel
// smem: [0..512) sIdx; [1024) Ah 4x16KB; [+64K) Al 4x16KB; [+128K) W 2x32KB
#define OFF_SIDX   0
#define OFF_AH     1024
#define OFF_AL     (1024 + 65536)
#define OFF_W      (1024 + 131072)
#define SMEM_MAIN  (OFF_W + 65536)          // 197632 B

// load one streamed weight k-tile ([n=128][k=64] bf16 hi+lo) via cp.async.
// tile index g in [0,24): g = nc*6 + t; t<4 -> W1 k-tile, t>=4 -> W2 k-tile.
__device__ __forceinline__ void loadW(uint32_t sb, int g, int tbase, int tid) {
    int nc = g / 6;
    int t  = g - nc * 6;
    uint32_t wb = sb + OFF_W + (uint32_t)(g & 1) * 32768u;
    const __nv_bfloat16 *sh, *sl;
    size_t base;
    int stride;
    if (t < 4) {
        sh = g_w1h; sl = g_w1l;
        base = (size_t)(nc * 128) * 256 + t * 64;
        stride = 256;
    } else {
        sh = g_w2h; sl = g_w2l;
        base = (size_t)tbase * 512 + nc * 128 + (t - 4) * 64;
        stride = 512;
    }
    #pragma unroll
    for (int it = 0; it < 4; it++) {
        int slot = tid + it * 256;
        int r = slot >> 3, c = slot & 7;
        uint32_t off = swz((uint32_t)(r * 128 + c * 16));
        const __nv_bfloat16* s1 = sh + base + (size_t)r * stride + c * 8;
        const __nv_bfloat16* s2 = sl + base + (size_t)r * stride + c * 8;
        cpa16(wb + off, s1);
        cpa16(wb + 16384 + off, s2);
    }
}

__global__ __launch_bounds__(256, 1)
void k_main(const float* __restrict__ fromE, const float* __restrict__ toE,
            const float* __restrict__ b1, const float* __restrict__ b2,
            float* __restrict__ out) {
    extern __shared__ char smem[];
    const uint32_t sb = smem_u32(smem);
    const int tid = threadIdx.x;
    const int warp = tid >> 5, lane = tid & 31;

    const int p0 = blockIdx.x * 128;
    if (p0 >= g_off[8]) return;

    int type = 0;
    #pragma unroll
    for (int t = 1; t < 8; t++)
        if (p0 >= g_off[t]) type = t;
    const int tbase = type * 128;

    // kick off first weight tile while we gather A
    loadW(sb, 0, tbase, tid);
    cp_commit();

    int* sIdx = (int*)(smem + OFF_SIDX);
    if (tid < 128) sIdx[tid] = g_perm[p0 + tid];
    __syncthreads();

    // ---- gather A rows, split fp32 -> bf16 hi/lo, SW128 k-tiles [st][m][k']
    {
        const int m = tid >> 1, hf = tid & 1;
        const int e = sIdx[m];
        const float* src = (hf ? toE : fromE) + (size_t)(e >= 0 ? e : 0) * 128;
        char* ah = smem + OFF_AH;
        char* al = smem + OFF_AL;
        #pragma unroll 8
        for (int q = 0; q < 32; q++) {
            float4 v = make_float4(0.f, 0.f, 0.f, 0.f);
            if (e >= 0) v = *(const float4*)(src + q * 4);
            int k = hf * 128 + q * 4;
            int st = k >> 6, ck = k & 63;
            uint32_t h0, l0, h1, l1;
            split2(v.x, v.y, h0, l0);
            split2(v.z, v.w, h1, l1);
            uint32_t off = swz((uint32_t)(m * 128 + ck * 2));
            *(uint2*)(ah + st * 16384 + off) = make_uint2(h0, h1);
            *(uint2*)(al + st * 16384 + off) = make_uint2(l0, l1);
        }
    }

    // fragment addressing constants
    const int arow = warp * 16 + (lane & 15);       // A ldmatrix row
    const int akh  = (lane >> 4) * 8;               // A k-half select
    const int brow = ((lane >> 3) & 2) * 4 + (lane & 7);  // B ldmatrix n-row
    const int bkh  = ((lane >> 3) & 1) * 8;         // B k-half select
    const int tq2  = 2 * (lane & 3);                // 2t (column pair base)

    float Oacc[16][4];
    #pragma unroll
    for (int j = 0; j < 16; j++)
        #pragma unroll
        for (int q = 0; q < 4; q++) Oacc[j][q] = 0.f;

    #pragma unroll 1
    for (int nc = 0; nc < 4; nc++) {
        float Hacc[16][4];
        #pragma unroll
        for (int j = 0; j < 16; j++)
            #pragma unroll
            for (int q = 0; q < 4; q++) Hacc[j][q] = 0.f;

        // ======== GEMM1: 4 W1 k-tiles ========
        #pragma unroll 1
        for (int kt = 0; kt < 4; kt++) {
            const int g = nc * 6 + kt;
            if (g + 1 < 24) { loadW(sb, g + 1, tbase, tid); cp_commit(); cp_wait1(); }
            else cp_wait0();
            __syncthreads();

            const uint32_t wbu = sb + OFF_W + (uint32_t)(g & 1) * 32768u;
            const uint32_t abh = sb + OFF_AH + (uint32_t)kt * 16384u;
            const uint32_t abl = sb + OFF_AL + (uint32_t)kt * 16384u;
            #pragma unroll
            for (int ks = 0; ks < 4; ks++) {
                uint32_t ah[4], al[4];
                uint32_t aoff = swz((uint32_t)(arow * 128 + (ks * 16 + akh) * 2));
                ldsm4(ah, abh + aoff);
                ldsm4(al, abl + aoff);
                #pragma unroll
                for (int jp = 0; jp < 8; jp++) {
                    uint32_t bh[4], bl[4];
                    uint32_t boff = swz((uint32_t)((jp * 16 + brow) * 128 +
                                                   (ks * 16 + bkh) * 2));
                    ldsm4(bh, wbu + boff);
                    ldsm4(bl, wbu + 16384u + boff);
                    mma16816(Hacc[2 * jp],     ah, bh[0], bh[1]);
                    mma16816(Hacc[2 * jp],     al, bh[0], bh[1]);
                    mma16816(Hacc[2 * jp],     ah, bl[0], bl[1]);
                    mma16816(Hacc[2 * jp + 1], ah, bh[2], bh[3]);
                    mma16816(Hacc[2 * jp + 1], al, bh[2], bh[3]);
                    mma16816(Hacc[2 * jp + 1], ah, bl[2], bl[3]);
                }
            }
            __syncthreads();
        }

        // ======== bias + ReLU + split -> H fragments in registers ========
        uint32_t Hh[32], Hl[32];
        #pragma unroll
        for (int j = 0; j < 16; j++) {
            float2 bb = __ldg((const float2*)(b1 + nc * 128 + 8 * j + tq2));
            float x0 = fmaxf(Hacc[j][0] + bb.x, 0.f);
            float x1 = fmaxf(Hacc[j][1] + bb.y, 0.f);
            float x2 = fmaxf(Hacc[j][2] + bb.x, 0.f);
            float x3 = fmaxf(Hacc[j][3] + bb.y, 0.f);
            split2(x0, x1, Hh[2 * j], Hl[2 * j]);
            split2(x2, x3, Hh[2 * j + 1], Hl[2 * j + 1]);
        }

        // ======== GEMM2: 2 W2 k-tiles, A from registers ========
        #pragma unroll
        for (int kt2 = 0; kt2 < 2; kt2++) {
            const int g = nc * 6 + 4 + kt2;
            if (g + 1 < 24) { loadW(sb, g + 1, tbase, tid); cp_commit(); cp_wait1(); }
            else cp_wait0();
            __syncthreads();

            const uint32_t wbu = sb + OFF_W + (uint32_t)(g & 1) * 32768u;
            #pragma unroll
            for (int ks = 0; ks < 4; ks++) {
                const int s = kt2 * 4 + ks;
                uint32_t ah[4] = {Hh[4*s], Hh[4*s+1], Hh[4*s+2], Hh[4*s+3]};
                uint32_t al[4] = {Hl[4*s], Hl[4*s+1], Hl[4*s+2], Hl[4*s+3]};
                #pragma unroll
                for (int jp = 0; jp < 8; jp++) {
                    uint32_t bh[4], bl[4];
                    uint32_t boff = swz((uint32_t)((jp * 16 + brow) * 128 +
                                                   (ks * 16 + bkh) * 2));
                    ldsm4(bh, wbu + boff);
                    ldsm4(bl, wbu + 16384u + boff);
                    mma16816(Oacc[2 * jp],     ah, bh[0], bh[1]);
                    mma16816(Oacc[2 * jp],     al, bh[0], bh[1]);
                    mma16816(Oacc[2 * jp],     ah, bl[0], bl[1]);
                    mma16816(Oacc[2 * jp + 1], ah, bh[2], bh[3]);
                    mma16816(Oacc[2 * jp + 1], al, bh[2], bh[3]);
                    mma16816(Oacc[2 * jp + 1], ah, bl[2], bl[3]);
                }
            }
            __syncthreads();
        }
    }

    // ======== epilogue: + b2 slice, scatter to original edge rows ========
    const int r0 = warp * 16 + (lane >> 2);
    const int e0 = sIdx[r0];
    const int e1 = sIdx[r0 + 8];
    #pragma unroll
    for (int j = 0; j < 16; j++) {
        float2 bb = __ldg((const float2*)(b2 + tbase + 8 * j + tq2));
        if (e0 >= 0) {
            float2 v = make_float2(Oacc[j][0] + bb.x, Oacc[j][1] + bb.y);
            *(float2*)(out + (size_t)e0 * 128 + 8 * j + tq2) = v;
        }
        if (e1 >= 0) {
            float2 v = make_float2(Oacc[j][2] + bb.x, Oacc[j][3] + bb.y);
            *(float2*)(out + (size_t)e1 * 128 + 8 * j + tq2) = v;
        }
    }
}

// ---------------------------------------------------------------- launch
extern "C" void kernel_launch(void* const* d_in, const int* in_sizes, int n_in,
                              void* d_out, int out_size) {
    const float* fromE = (const float*)d_in[0];
    const float* toE   = (const float*)d_in[1];
    const void*  et    = d_in[2];
    const float* W1    = (const float*)d_in[3];
    const float* b1    = (const float*)d_in[4];
    const float* W2    = (const float*)d_in[5];
    const float* b2    = (const float*)d_in[6];
    float* out = (float*)d_out;

    const int E = in_sizes[0] / 128;
    const int padcap = E + 8 * 128;

    cudaFuncSetAttribute(k_main, cudaFuncAttributeMaxDynamicSharedMemorySize,
                         SMEM_MAIN);

    k_detect<<<1, 32>>>((const int*)et, E);
    k_fill<<<(padcap + 255) / 256, 256>>>(padcap);
    k_count<<<(E + 255) / 256, 256>>>(et, E);
    k_scan<<<1, 32>>>();
    k_scatter<<<(E + 255) / 256, 256>>>(et, E);
    k_convw<<<(512 * 1024 + 255) / 256, 256>>>(W1, W2);

    const int nMain = (E >> 7) + 9;
    k_main<<<nMain, 256, SMEM_MAIN>>>(fromE, toE, b1, b2, out);
}